// round 2
// baseline (speedup 1.0000x reference)
#include <cuda_runtime.h>
#include <math_constants.h>

// Problem shape: decoder_state (32,512) f32, encoder_hiddens (32,8192,512) f32
#define BATCH 32
#define SEQ   8192
#define DIM   512
#define DIM4  (DIM / 4)        // 128 float4 per row

#define CHUNKS 32              // S-chunks per batch
#define ROWS_PER_CHUNK (SEQ / CHUNKS)   // 256
#define WARPS_PER_BLOCK 8
#define THREADS_PER_BLOCK (WARPS_PER_BLOCK * 32)   // 256
#define ROWS_PER_WARP (ROWS_PER_CHUNK / WARPS_PER_BLOCK)  // 32

// Scratch for partial results (allocation-free: __device__ globals)
__device__ float  g_partial_ctx[BATCH * CHUNKS * DIM];   // 2 MB
__device__ float2 g_partial_ml[BATCH * CHUNKS];          // (m, l) per partial

// ---------------------------------------------------------------------------
// Pass 1: one block per (batch, chunk). Each warp streams ROWS_PER_WARP rows
// TWO AT A TIME (8 independent LDG.128 per iteration for MLP), doing
// online-softmax score + context accumulation in a single HBM read.
// ---------------------------------------------------------------------------
__global__ __launch_bounds__(THREADS_PER_BLOCK)
void luong_pass1(const float* __restrict__ dec, const float* __restrict__ enc)
{
    const int b     = blockIdx.x / CHUNKS;
    const int chunk = blockIdx.x % CHUNKS;
    const int warp  = threadIdx.x >> 5;
    const int lane  = threadIdx.x & 31;

    // Decoder slice for this lane: float4 indices lane + 32*j, j = 0..3
    const float4* dec4 = reinterpret_cast<const float4*>(dec) + (size_t)b * DIM4;
    float4 dq[4];
#pragma unroll
    for (int j = 0; j < 4; j++) dq[j] = dec4[lane + 32 * j];

    // Online softmax state (per warp, context sharded across lanes)
    float m = -CUDART_INF_F;
    float l = 0.0f;
    float4 ctx[4];
#pragma unroll
    for (int j = 0; j < 4; j++) ctx[j] = make_float4(0.f, 0.f, 0.f, 0.f);

    const int s0 = chunk * ROWS_PER_CHUNK + warp * ROWS_PER_WARP;
    const float4* enc4 = reinterpret_cast<const float4*>(enc)
                       + ((size_t)b * SEQ + s0) * DIM4;

    for (int i = 0; i < ROWS_PER_WARP; i += 2) {
        const float4* row0 = enc4 + (size_t)i * DIM4;
        const float4* row1 = row0 + DIM4;
        // Front-batched loads: 8 independent LDG.128 per lane
        float4 r0[4], r1[4];
#pragma unroll
        for (int j = 0; j < 4; j++) r0[j] = row0[lane + 32 * j];
#pragma unroll
        for (int j = 0; j < 4; j++) r1[j] = row1[lane + 32 * j];

        // Lane-local partial dot products (independent chains)
        float dot0 = 0.0f, dot1 = 0.0f;
#pragma unroll
        for (int j = 0; j < 4; j++) {
            dot0 = fmaf(r0[j].x, dq[j].x, dot0);
            dot0 = fmaf(r0[j].y, dq[j].y, dot0);
            dot0 = fmaf(r0[j].z, dq[j].z, dot0);
            dot0 = fmaf(r0[j].w, dq[j].w, dot0);
            dot1 = fmaf(r1[j].x, dq[j].x, dot1);
            dot1 = fmaf(r1[j].y, dq[j].y, dot1);
            dot1 = fmaf(r1[j].z, dq[j].z, dot1);
            dot1 = fmaf(r1[j].w, dq[j].w, dot1);
        }
        // Butterfly all-reduce both scores (interleaved, independent)
#pragma unroll
        for (int o = 16; o > 0; o >>= 1) {
            dot0 += __shfl_xor_sync(0xFFFFFFFFu, dot0, o);
            dot1 += __shfl_xor_sync(0xFFFFFFFFu, dot1, o);
        }

        // Online softmax update: one rescale per TWO rows
        const float m_new = fmaxf(m, fmaxf(dot0, dot1));
        const float scale = __expf(m - m_new);   // exp(-inf)=0 on first iter
        const float p0    = __expf(dot0 - m_new);
        const float p1    = __expf(dot1 - m_new);
        l = fmaf(l, scale, p0 + p1);
        m = m_new;
#pragma unroll
        for (int j = 0; j < 4; j++) {
            ctx[j].x = fmaf(ctx[j].x, scale, fmaf(p0, r0[j].x, p1 * r1[j].x));
            ctx[j].y = fmaf(ctx[j].y, scale, fmaf(p0, r0[j].y, p1 * r1[j].y));
            ctx[j].z = fmaf(ctx[j].z, scale, fmaf(p0, r0[j].z, p1 * r1[j].z));
            ctx[j].w = fmaf(ctx[j].w, scale, fmaf(p0, r0[j].w, p1 * r1[j].w));
        }
    }

    // ---- Combine the 8 warps' partials within the block ----
    __shared__ float  s_m[WARPS_PER_BLOCK];
    __shared__ float  s_l[WARPS_PER_BLOCK];
    __shared__ float4 s_ctx[WARPS_PER_BLOCK * DIM4];   // 16 KB

    if (lane == 0) { s_m[warp] = m; s_l[warp] = l; }
    __syncthreads();

    float m_blk = -CUDART_INF_F;
#pragma unroll
    for (int w = 0; w < WARPS_PER_BLOCK; w++) m_blk = fmaxf(m_blk, s_m[w]);

    const float wscale = __expf(m - m_blk);
#pragma unroll
    for (int j = 0; j < 4; j++) {
        float4 c = ctx[j];
        c.x *= wscale; c.y *= wscale; c.z *= wscale; c.w *= wscale;
        s_ctx[warp * DIM4 + lane + 32 * j] = c;
    }
    __syncthreads();

    const int pidx = b * CHUNKS + chunk;
    // 128 float4 positions; first 128 threads each reduce one across 8 warps
    if (threadIdx.x < DIM4) {
        float4 acc = make_float4(0.f, 0.f, 0.f, 0.f);
#pragma unroll
        for (int w = 0; w < WARPS_PER_BLOCK; w++) {
            float4 c = s_ctx[w * DIM4 + threadIdx.x];
            acc.x += c.x; acc.y += c.y; acc.z += c.z; acc.w += c.w;
        }
        reinterpret_cast<float4*>(g_partial_ctx)[(size_t)pidx * DIM4 + threadIdx.x] = acc;
    }
    if (threadIdx.x == 0) {
        float l_blk = 0.0f;
#pragma unroll
        for (int w = 0; w < WARPS_PER_BLOCK; w++)
            l_blk = fmaf(s_l[w], __expf(s_m[w] - m_blk), l_blk);
        g_partial_ml[pidx] = make_float2(m_blk, l_blk);
    }
}

// ---------------------------------------------------------------------------
// Pass 2: one block per batch; merge CHUNKS partials into the final context.
// ---------------------------------------------------------------------------
__global__ __launch_bounds__(DIM4)
void luong_pass2(float* __restrict__ out)
{
    const int b = blockIdx.x;
    const int t = threadIdx.x;   // 0..127 (one float4 each)

    __shared__ float s_scale[CHUNKS];
    __shared__ float s_rcpL;

    if (t == 0) {
        float M = -CUDART_INF_F;
        float2 ml[CHUNKS];
#pragma unroll
        for (int i = 0; i < CHUNKS; i++) {
            ml[i] = g_partial_ml[b * CHUNKS + i];
            M = fmaxf(M, ml[i].x);
        }
        float L = 0.0f;
#pragma unroll
        for (int i = 0; i < CHUNKS; i++) {
            float sc = __expf(ml[i].x - M);
            s_scale[i] = sc;
            L = fmaf(ml[i].y, sc, L);
        }
        s_rcpL = 1.0f / L;
    }
    __syncthreads();

    float4 acc = make_float4(0.f, 0.f, 0.f, 0.f);
    const float4* pctx = reinterpret_cast<const float4*>(g_partial_ctx)
                       + (size_t)b * CHUNKS * DIM4 + t;
#pragma unroll
    for (int i = 0; i < CHUNKS; i++) {
        const float sc = s_scale[i];
        float4 c = pctx[(size_t)i * DIM4];
        acc.x = fmaf(c.x, sc, acc.x);
        acc.y = fmaf(c.y, sc, acc.y);
        acc.z = fmaf(c.z, sc, acc.z);
        acc.w = fmaf(c.w, sc, acc.w);
    }
    const float r = s_rcpL;
    acc.x *= r; acc.y *= r; acc.z *= r; acc.w *= r;
    reinterpret_cast<float4*>(out)[(size_t)b * DIM4 + t] = acc;
}

// ---------------------------------------------------------------------------
extern "C" void kernel_launch(void* const* d_in, const int* in_sizes, int n_in,
                              void* d_out, int out_size)
{
    const float* dec = (const float*)d_in[0];   // (32, 512)
    const float* enc = (const float*)d_in[1];   // (32, 8192, 512)
    float* out = (float*)d_out;                 // (32, 512)

    luong_pass1<<<BATCH * CHUNKS, THREADS_PER_BLOCK>>>(dec, enc);
    luong_pass2<<<BATCH, DIM4>>>(out);
}

// round 3
// speedup vs baseline: 1.1194x; 1.1194x over previous
#include <cuda_runtime.h>
#include <math_constants.h>

// Problem shape: decoder_state (32,512) f32, encoder_hiddens (32,8192,512) f32
#define BATCH 32
#define SEQ   8192
#define DIM   512
#define DIM4  (DIM / 4)        // 128 float4 per row

#define CHUNKS 64              // S-chunks per batch (finer tail granularity)
#define ROWS_PER_CHUNK (SEQ / CHUNKS)   // 128
#define WARPS_PER_BLOCK 8
#define THREADS_PER_BLOCK (WARPS_PER_BLOCK * 32)   // 256
#define ROWS_PER_WARP (ROWS_PER_CHUNK / WARPS_PER_BLOCK)  // 16

// Scratch for partial results (allocation-free: __device__ globals)
__device__ float  g_partial_ctx[BATCH * CHUNKS * DIM];   // 4 MB
__device__ float2 g_partial_ml[BATCH * CHUNKS];          // (m, l) per partial

// ---------------------------------------------------------------------------
// Pass 1: one block per (batch, chunk). Each warp streams ROWS_PER_WARP rows
// TWO AT A TIME (8 independent LDG.128 per iteration for MLP), doing
// online-softmax score + context accumulation in a single HBM read.
// ---------------------------------------------------------------------------
__global__ __launch_bounds__(THREADS_PER_BLOCK)
void luong_pass1(const float* __restrict__ dec, const float* __restrict__ enc)
{
    const int b     = blockIdx.x / CHUNKS;
    const int chunk = blockIdx.x % CHUNKS;
    const int warp  = threadIdx.x >> 5;
    const int lane  = threadIdx.x & 31;

    // Decoder slice for this lane: float4 indices lane + 32*j, j = 0..3
    const float4* dec4 = reinterpret_cast<const float4*>(dec) + (size_t)b * DIM4;
    float4 dq[4];
#pragma unroll
    for (int j = 0; j < 4; j++) dq[j] = dec4[lane + 32 * j];

    // Online softmax state (per warp, context sharded across lanes)
    float m = -CUDART_INF_F;
    float l = 0.0f;
    float4 ctx[4];
#pragma unroll
    for (int j = 0; j < 4; j++) ctx[j] = make_float4(0.f, 0.f, 0.f, 0.f);

    const int s0 = chunk * ROWS_PER_CHUNK + warp * ROWS_PER_WARP;
    const float4* enc4 = reinterpret_cast<const float4*>(enc)
                       + ((size_t)b * SEQ + s0) * DIM4;

    for (int i = 0; i < ROWS_PER_WARP; i += 2) {
        const float4* row0 = enc4 + (size_t)i * DIM4;
        const float4* row1 = row0 + DIM4;
        // Front-batched loads: 8 independent LDG.128 per lane
        float4 r0[4], r1[4];
#pragma unroll
        for (int j = 0; j < 4; j++) r0[j] = row0[lane + 32 * j];
#pragma unroll
        for (int j = 0; j < 4; j++) r1[j] = row1[lane + 32 * j];

        // Lane-local partial dot products (independent chains)
        float dot0 = 0.0f, dot1 = 0.0f;
#pragma unroll
        for (int j = 0; j < 4; j++) {
            dot0 = fmaf(r0[j].x, dq[j].x, dot0);
            dot0 = fmaf(r0[j].y, dq[j].y, dot0);
            dot0 = fmaf(r0[j].z, dq[j].z, dot0);
            dot0 = fmaf(r0[j].w, dq[j].w, dot0);
            dot1 = fmaf(r1[j].x, dq[j].x, dot1);
            dot1 = fmaf(r1[j].y, dq[j].y, dot1);
            dot1 = fmaf(r1[j].z, dq[j].z, dot1);
            dot1 = fmaf(r1[j].w, dq[j].w, dot1);
        }
        // Butterfly all-reduce both scores (interleaved, independent)
#pragma unroll
        for (int o = 16; o > 0; o >>= 1) {
            dot0 += __shfl_xor_sync(0xFFFFFFFFu, dot0, o);
            dot1 += __shfl_xor_sync(0xFFFFFFFFu, dot1, o);
        }

        // Online softmax update: one rescale per TWO rows
        const float m_new = fmaxf(m, fmaxf(dot0, dot1));
        const float scale = __expf(m - m_new);   // exp(-inf)=0 on first iter
        const float p0    = __expf(dot0 - m_new);
        const float p1    = __expf(dot1 - m_new);
        l = fmaf(l, scale, p0 + p1);
        m = m_new;
#pragma unroll
        for (int j = 0; j < 4; j++) {
            ctx[j].x = fmaf(ctx[j].x, scale, fmaf(p0, r0[j].x, p1 * r1[j].x));
            ctx[j].y = fmaf(ctx[j].y, scale, fmaf(p0, r0[j].y, p1 * r1[j].y));
            ctx[j].z = fmaf(ctx[j].z, scale, fmaf(p0, r0[j].z, p1 * r1[j].z));
            ctx[j].w = fmaf(ctx[j].w, scale, fmaf(p0, r0[j].w, p1 * r1[j].w));
        }
    }

    // ---- Combine the 8 warps' partials within the block ----
    __shared__ float  s_m[WARPS_PER_BLOCK];
    __shared__ float  s_l[WARPS_PER_BLOCK];
    __shared__ float4 s_ctx[WARPS_PER_BLOCK * DIM4];   // 16 KB

    if (lane == 0) { s_m[warp] = m; s_l[warp] = l; }
    __syncthreads();

    float m_blk = -CUDART_INF_F;
#pragma unroll
    for (int w = 0; w < WARPS_PER_BLOCK; w++) m_blk = fmaxf(m_blk, s_m[w]);

    const float wscale = __expf(m - m_blk);
#pragma unroll
    for (int j = 0; j < 4; j++) {
        float4 c = ctx[j];
        c.x *= wscale; c.y *= wscale; c.z *= wscale; c.w *= wscale;
        s_ctx[warp * DIM4 + lane + 32 * j] = c;
    }
    __syncthreads();

    const int pidx = b * CHUNKS + chunk;
    // 128 float4 positions; first 128 threads each reduce one across 8 warps
    if (threadIdx.x < DIM4) {
        float4 acc = make_float4(0.f, 0.f, 0.f, 0.f);
#pragma unroll
        for (int w = 0; w < WARPS_PER_BLOCK; w++) {
            float4 c = s_ctx[w * DIM4 + threadIdx.x];
            acc.x += c.x; acc.y += c.y; acc.z += c.z; acc.w += c.w;
        }
        reinterpret_cast<float4*>(g_partial_ctx)[(size_t)pidx * DIM4 + threadIdx.x] = acc;
    }
    if (threadIdx.x == 0) {
        float l_blk = 0.0f;
#pragma unroll
        for (int w = 0; w < WARPS_PER_BLOCK; w++)
            l_blk = fmaf(s_l[w], __expf(s_m[w] - m_blk), l_blk);
        g_partial_ml[pidx] = make_float2(m_blk, l_blk);
    }
}

// ---------------------------------------------------------------------------
// Pass 2: one WARP per output float4 (4096 warps = 512 blocks x 256 threads).
// Lane l owns chunks l and l+32. Each warp redundantly computes (M, L) from
// g_partial_ml fully in-register (butterfly reduces) -- no smem, no serial
// section, massively parallel vs the old 32-block version.
// ---------------------------------------------------------------------------
#define P2_WARPS 8
__global__ __launch_bounds__(P2_WARPS * 32)
void luong_pass2(float* __restrict__ out)
{
    const int warp = threadIdx.x >> 5;
    const int lane = threadIdx.x & 31;
    const int wg   = blockIdx.x * P2_WARPS + warp;   // 0 .. BATCH*DIM4-1
    const int b    = wg / DIM4;
    const int pos  = wg % DIM4;

    // Per-lane (m,l) for chunks lane and lane+32
    const float2 ml0 = g_partial_ml[b * CHUNKS + lane];
    const float2 ml1 = g_partial_ml[b * CHUNKS + lane + 32];

    // Warp-wide max M
    float M = fmaxf(ml0.x, ml1.x);
#pragma unroll
    for (int o = 16; o > 0; o >>= 1)
        M = fmaxf(M, __shfl_xor_sync(0xFFFFFFFFu, M, o));

    const float sc0 = __expf(ml0.x - M);
    const float sc1 = __expf(ml1.x - M);

    // Warp-wide L
    float L = fmaf(ml0.y, sc0, ml1.y * sc1);
#pragma unroll
    for (int o = 16; o > 0; o >>= 1)
        L += __shfl_xor_sync(0xFFFFFFFFu, L, o);

    // Scaled context contributions for this lane's two chunks
    const float4* pctx = reinterpret_cast<const float4*>(g_partial_ctx)
                       + (size_t)b * CHUNKS * DIM4 + pos;
    const float4 c0 = pctx[(size_t)lane * DIM4];
    const float4 c1 = pctx[(size_t)(lane + 32) * DIM4];

    float4 acc;
    acc.x = fmaf(c0.x, sc0, c1.x * sc1);
    acc.y = fmaf(c0.y, sc0, c1.y * sc1);
    acc.z = fmaf(c0.z, sc0, c1.z * sc1);
    acc.w = fmaf(c0.w, sc0, c1.w * sc1);

    // Butterfly sum across lanes (sums all 64 chunks)
#pragma unroll
    for (int o = 16; o > 0; o >>= 1) {
        acc.x += __shfl_xor_sync(0xFFFFFFFFu, acc.x, o);
        acc.y += __shfl_xor_sync(0xFFFFFFFFu, acc.y, o);
        acc.z += __shfl_xor_sync(0xFFFFFFFFu, acc.z, o);
        acc.w += __shfl_xor_sync(0xFFFFFFFFu, acc.w, o);
    }

    if (lane == 0) {
        const float r = 1.0f / L;
        acc.x *= r; acc.y *= r; acc.z *= r; acc.w *= r;
        reinterpret_cast<float4*>(out)[(size_t)b * DIM4 + pos] = acc;
    }
}

// ---------------------------------------------------------------------------
extern "C" void kernel_launch(void* const* d_in, const int* in_sizes, int n_in,
                              void* d_out, int out_size)
{
    const float* dec = (const float*)d_in[0];   // (32, 512)
    const float* enc = (const float*)d_in[1];   // (32, 8192, 512)
    float* out = (float*)d_out;                 // (32, 512)

    luong_pass1<<<BATCH * CHUNKS, THREADS_PER_BLOCK>>>(dec, enc);
    luong_pass2<<<(BATCH * DIM4) / P2_WARPS, P2_WARPS * 32>>>(out);
}